// round 16
// baseline (speedup 1.0000x reference)
#include <cuda_runtime.h>
#include <cuda_fp16.h>
#include <cstdint>
#include <math.h>

// ---------------------------------------------------------------------------
// Problem dims (fixed by the dataset)
// ---------------------------------------------------------------------------
#define B_MAX   32768
#define CIN     512
#define H1      2048
#define H2      1024
#define COUT    256
#define PDIM    8

// ---------------------------------------------------------------------------
// Scratch (__device__ globals: the sanctioned no-alloc workaround)
// ---------------------------------------------------------------------------
__device__ __half g_h1[B_MAX * 32];
__device__ __half g_h2[B_MAX * 32];
__device__ __half g_h3[B_MAX * 32];
__device__ __half g_h4[B_MAX * 32];
__device__ __half g_xfh[(size_t)B_MAX * CIN];
__device__ __half g_x1h[(size_t)B_MAX * H1];
__device__ __half g_x2h[(size_t)B_MAX * H2];
__device__ float  g_x3[(size_t)B_MAX * COUT];
__device__ float  g_stats[4 * B_MAX];          // ssum1, ssq1, ssum2, ssq2
// transposed fp16 weights [N, K]
__device__ __half g_l1wt[(size_t)H1 * CIN];
__device__ __half g_l2wt[(size_t)H2 * H1];
__device__ __half g_l3wt[(size_t)COUT * H2];
__device__ __half g_hw12t[H1 * 32];
__device__ __half g_hb12t[H1 * 32];
__device__ __half g_hw22t[H2 * 32];
__device__ __half g_hb22t[H2 * 32];

// ---------------------------------------------------------------------------
// Helpers (all architecture-portable PTX: sm_80+)
// ---------------------------------------------------------------------------
__device__ __forceinline__ uint32_t smem_u32(const void* p)
{
    uint32_t a;
    asm("{ .reg .u64 t; cvta.to.shared.u64 t, %1; cvt.u32.u64 %0, t; }"
        : "=r"(a) : "l"(p));
    return a;
}

__device__ __forceinline__ void cp_async16(uint32_t dst, const void* src)
{
    asm volatile("cp.async.cg.shared.global [%0], [%1], 16;"
                 :: "r"(dst), "l"(src));
}
__device__ __forceinline__ void cp_commit()
{
    asm volatile("cp.async.commit_group;" ::: "memory");
}
template <int N>
__device__ __forceinline__ void cp_wait()
{
    asm volatile("cp.async.wait_group %0;" :: "n"(N) : "memory");
}

// fp16 m16n8k16 mma, fp32 accumulate (portable since sm_80)
__device__ __forceinline__ void mma16(float* d, const uint32_t* a, const uint32_t* b)
{
    asm volatile(
        "mma.sync.aligned.m16n8k16.row.col.f32.f16.f16.f32 "
        "{%0,%1,%2,%3}, {%4,%5,%6,%7}, {%8,%9}, {%0,%1,%2,%3};"
        : "+f"(d[0]), "+f"(d[1]), "+f"(d[2]), "+f"(d[3])
        : "r"(a[0]), "r"(a[1]), "r"(a[2]), "r"(a[3]), "r"(b[0]), "r"(b[1]));
}

__device__ __forceinline__ void ldsm4(uint32_t* r, uint32_t addr)
{
    asm volatile("ldmatrix.sync.aligned.m8n8.x4.shared.b16 {%0,%1,%2,%3}, [%4];"
                 : "=r"(r[0]), "=r"(r[1]), "=r"(r[2]), "=r"(r[3]) : "r"(addr));
}

// ---------------------------------------------------------------------------
// fp16 tensor-core GEMM (champion config):  C = A @ Bt^T + bias
// BM=BN=128, BK=64; 128 threads = 4 warps (2x2), 64x64 per warp.
// 2-stage double buffer. Optional per-row sum/sumsq accumulation (for GN).
// ---------------------------------------------------------------------------
template <typename OutT>
__global__ __launch_bounds__(128, 2) void gemm_h(
    int M, int N, int K,
    const __half* __restrict__ A, const __half* __restrict__ Bt,
    const float* __restrict__ bias, OutT* __restrict__ C,
    float* __restrict__ ssum, float* __restrict__ ssq)
{
    constexpr int BKH = 64;
    constexpr int LDH = BKH + 8;
    constexpr int A_H = 128 * LDH;
    constexpr int STAGE_H = 256 * LDH;
    constexpr int CPR = BKH / 8;
    constexpr int KS = BKH / 16;

    extern __shared__ __half smh[];          // [2][STAGE_H]

    const int tid = threadIdx.x;
    const int lane = tid & 31, wid = tid >> 5;
    const int wm = wid & 1, wn = wid >> 1;
    const int m0 = blockIdx.y * 128;
    const int n0 = blockIdx.x * 128;
    const int nkt = K / BKH;

    const __half* Ag = A + (size_t)m0 * K;
    const __half* Bg = Bt + (size_t)n0 * K;
    const uint32_t sS = smem_u32(smh);

    const uint32_t a_off =
        (uint32_t)(((wm * 64 + (lane & 15)) * LDH + ((lane >> 4) << 3)) * 2);
    const uint32_t b_off =
        (uint32_t)(((wn * 64 + ((lane >> 4) << 3) + (lane & 7)) * LDH +
                    (((lane >> 3) & 1) << 3)) * 2);

    float acc[4][8][4];
#pragma unroll
    for (int mt = 0; mt < 4; mt++)
#pragma unroll
        for (int nt = 0; nt < 8; nt++)
#pragma unroll
            for (int j = 0; j < 4; j++) acc[mt][nt][j] = 0.0f;

    auto load_tiles = [&](int t) {
        const uint32_t base = sS + (uint32_t)((t & 1) * (STAGE_H * 2));
        const __half* ga = Ag + t * BKH;
        const __half* gb = Bg + t * BKH;
#pragma unroll
        for (int it = 0; it < CPR; it++) {
            int idx = tid + it * 128;
            int r = idx / CPR, cc = idx % CPR;
            uint32_t off = r * (LDH * 2) + cc * 16;
            cp_async16(base + off, ga + (size_t)r * K + cc * 8);
            cp_async16(base + A_H * 2 + off, gb + (size_t)r * K + cc * 8);
        }
    };

    load_tiles(0);
    cp_commit();

    for (int i = 0; i < nkt; i++) {
        if (i + 1 < nkt) {
            load_tiles(i + 1);
            cp_commit();
            cp_wait<1>();
        } else {
            cp_wait<0>();
        }
        __syncthreads();

        const uint32_t st = sS + (uint32_t)((i & 1) * (STAGE_H * 2));
        const uint32_t sa = st + a_off;
        const uint32_t sb = st + (uint32_t)(A_H * 2) + b_off;

#pragma unroll
        for (int ks = 0; ks < KS; ks++) {
            uint32_t af[4][4], bf[4][4];
#pragma unroll
            for (int mt = 0; mt < 4; mt++)
                ldsm4(af[mt], sa + (uint32_t)((mt * 16 * LDH + ks * 16) * 2));
#pragma unroll
            for (int np = 0; np < 4; np++)
                ldsm4(bf[np], sb + (uint32_t)((np * 16 * LDH + ks * 16) * 2));
#pragma unroll
            for (int mt = 0; mt < 4; mt++)
#pragma unroll
                for (int nt = 0; nt < 8; nt++)
                    mma16(acc[mt][nt], af[mt], bf[nt >> 1] + (nt & 1) * 2);
        }
        __syncthreads();
    }

    // ---- epilogue: bias + store (+ optional per-row stats via atomics) ----
    const int arow = lane >> 2;
    const int acol = lane & 3;
    float2 bv[8];
#pragma unroll
    for (int nt = 0; nt < 8; nt++) {
        int cc = n0 + wn * 64 + nt * 8 + acol * 2;
        bv[nt] = *(const float2*)&bias[cc];
    }
#pragma unroll
    for (int mt = 0; mt < 4; mt++) {
        size_t r0 = (size_t)m0 + wm * 64 + mt * 16 + arow;
        float s0 = 0.0f, q0 = 0.0f, s1 = 0.0f, q1 = 0.0f;
#pragma unroll
        for (int nt = 0; nt < 8; nt++) {
            int cc = n0 + wn * 64 + nt * 8 + acol * 2;
            float v00 = acc[mt][nt][0] + bv[nt].x;
            float v01 = acc[mt][nt][1] + bv[nt].y;
            float v10 = acc[mt][nt][2] + bv[nt].x;
            float v11 = acc[mt][nt][3] + bv[nt].y;
            s0 += v00 + v01; q0 += v00 * v00 + v01 * v01;
            s1 += v10 + v11; q1 += v10 * v10 + v11 * v11;
            if constexpr (sizeof(OutT) == 2) {
                *(__half2*)&C[r0 * N + cc] = __floats2half2_rn(v00, v01);
                *(__half2*)&C[(r0 + 8) * N + cc] = __floats2half2_rn(v10, v11);
            } else {
                float2 a0 = { v00, v01 }, a1 = { v10, v11 };
                *(float2*)&C[r0 * N + cc] = a0;
                *(float2*)&C[(r0 + 8) * N + cc] = a1;
            }
        }
        if (ssum != nullptr) {
#pragma unroll
            for (int o = 1; o <= 2; o <<= 1) {
                s0 += __shfl_xor_sync(0xffffffffu, s0, o);
                q0 += __shfl_xor_sync(0xffffffffu, q0, o);
                s1 += __shfl_xor_sync(0xffffffffu, s1, o);
                q1 += __shfl_xor_sync(0xffffffffu, q1, o);
            }
            if (acol == 0) {
                atomicAdd(&ssum[r0], s0);
                atomicAdd(&ssq[r0], q0);
                atomicAdd(&ssum[r0 + 8], s1);
                atomicAdd(&ssq[r0 + 8], q1);
            }
        }
    }
}

// ---------------------------------------------------------------------------
// FULLY fused hypernet-output + groupnorm kernel (per layer):
//   b = h_b @ Wt_b^T + bias_b      (pass 1, stashed per-thread via smem)
//   w = h_w @ Wt_w^T + bias_w      (pass 2, in accumulators)
//   x = relu((x - mu_r)*rstd_r * w + b)      in place on x (fp16)
// Champion geometry (128 thr, 2x2 warps, 64x64), ONE accumulator set.
// Same-thread element mapping across passes => no syncs for the b stash.
// ---------------------------------------------------------------------------
__global__ __launch_bounds__(128, 2) void hyper_gn_fused(
    int M, int H,
    const __half* __restrict__ hw, const __half* __restrict__ hb,
    const __half* __restrict__ Wtw, const __half* __restrict__ Wtb,
    const float* __restrict__ bias_w, const float* __restrict__ bias_b,
    const float* __restrict__ ssum, const float* __restrict__ ssq,
    __half* x)
{
    constexpr int K = 32;
    constexpr int LDH = 40;
    constexpr int TILE_H = 128 * LDH;        // halves per tile

    extern __shared__ __half smd[];          // 4 tiles + b-stash
    __shared__ float stat[256];              // mu, rstd per local row

    const int tid = threadIdx.x;
    const int lane = tid & 31, wid = tid >> 5;
    const int wm = wid & 1, wn = wid >> 1;
    const int m0 = blockIdx.y * 128;
    const int n0 = blockIdx.x * 128;
    const uint32_t sS = smem_u32(smd);
    __half2* bsave = (__half2*)(smd + 4 * TILE_H);   // [128][64] half2

    // ---- one-shot tile loads: hw, hb (rows m0..), Wtw, Wtb (rows n0..) ----
    {
        const __half* srcs[4] = { hw + (size_t)m0 * K, hb + (size_t)m0 * K,
                                  Wtw + (size_t)n0 * K, Wtb + (size_t)n0 * K };
#pragma unroll
        for (int t4 = 0; t4 < 4; t4++) {
#pragma unroll
            for (int it = 0; it < 4; it++) {
                int idx = tid + it * 128;
                int r = idx >> 2, cc = idx & 3;
                cp_async16(sS + (uint32_t)(t4 * TILE_H * 2) + r * (LDH * 2) + cc * 16,
                           srcs[t4] + (size_t)r * K + cc * 8);
            }
        }
        cp_commit();
    }
    // row stats (overlaps cp.async)
    {
        float invH = 1.0f / (float)H;
        int r = m0 + tid;
        float mu = ssum[r] * invH;
        float var = ssq[r] * invH - mu * mu;
        stat[tid * 2] = mu;
        stat[tid * 2 + 1] = rsqrtf(var + 1e-5f);
    }

    const uint32_t a_off =
        (uint32_t)(((wm * 64 + (lane & 15)) * LDH + ((lane >> 4) << 3)) * 2);
    const uint32_t b_off =
        (uint32_t)(((wn * 64 + ((lane >> 4) << 3) + (lane & 7)) * LDH +
                    (((lane >> 3) & 1) << 3)) * 2);

    float acc[4][8][4];
#pragma unroll
    for (int mt = 0; mt < 4; mt++)
#pragma unroll
        for (int nt = 0; nt < 8; nt++)
#pragma unroll
            for (int j = 0; j < 4; j++) acc[mt][nt][j] = 0.0f;

    cp_wait<0>();
    __syncthreads();

    const int arow = lane >> 2;
    const int acol = lane & 3;

    // ======== pass 1: b = h_b @ Wt_b^T ========
    {
        const uint32_t sa = sS + (uint32_t)(1 * TILE_H * 2) + a_off;   // hb tile
        const uint32_t sb = sS + (uint32_t)(3 * TILE_H * 2) + b_off;   // Wtb tile
#pragma unroll
        for (int ks = 0; ks < 2; ks++) {
            uint32_t af[4][4], bf[4][4];
#pragma unroll
            for (int mt = 0; mt < 4; mt++)
                ldsm4(af[mt], sa + (uint32_t)((mt * 16 * LDH + ks * 16) * 2));
#pragma unroll
            for (int np = 0; np < 4; np++)
                ldsm4(bf[np], sb + (uint32_t)((np * 16 * LDH + ks * 16) * 2));
#pragma unroll
            for (int mt = 0; mt < 4; mt++)
#pragma unroll
                for (int nt = 0; nt < 8; nt++)
                    mma16(acc[mt][nt], af[mt], bf[nt >> 1] + (nt & 1) * 2);
        }
        // stash b + bias_b (same-thread consumption later; no sync needed)
        float2 bvb[8];
#pragma unroll
        for (int nt = 0; nt < 8; nt++) {
            int cc = n0 + wn * 64 + nt * 8 + acol * 2;
            bvb[nt] = *(const float2*)&bias_b[cc];
        }
#pragma unroll
        for (int mt = 0; mt < 4; mt++) {
            int rl = wm * 64 + mt * 16 + arow;
#pragma unroll
            for (int nt = 0; nt < 8; nt++) {
                int ccl = wn * 64 + nt * 8 + acol * 2;
                bsave[rl * 64 + (ccl >> 1)] =
                    __floats2half2_rn(acc[mt][nt][0] + bvb[nt].x,
                                      acc[mt][nt][1] + bvb[nt].y);
                bsave[(rl + 8) * 64 + (ccl >> 1)] =
                    __floats2half2_rn(acc[mt][nt][2] + bvb[nt].x,
                                      acc[mt][nt][3] + bvb[nt].y);
                acc[mt][nt][0] = 0.0f; acc[mt][nt][1] = 0.0f;
                acc[mt][nt][2] = 0.0f; acc[mt][nt][3] = 0.0f;
            }
        }
    }

    // ======== pass 2: w = h_w @ Wt_w^T ========
    {
        const uint32_t sa = sS + a_off;                                // hw tile
        const uint32_t sb = sS + (uint32_t)(2 * TILE_H * 2) + b_off;   // Wtw tile
#pragma unroll
        for (int ks = 0; ks < 2; ks++) {
            uint32_t af[4][4], bf[4][4];
#pragma unroll
            for (int mt = 0; mt < 4; mt++)
                ldsm4(af[mt], sa + (uint32_t)((mt * 16 * LDH + ks * 16) * 2));
#pragma unroll
            for (int np = 0; np < 4; np++)
                ldsm4(bf[np], sb + (uint32_t)((np * 16 * LDH + ks * 16) * 2));
#pragma unroll
            for (int mt = 0; mt < 4; mt++)
#pragma unroll
                for (int nt = 0; nt < 8; nt++)
                    mma16(acc[mt][nt], af[mt], bf[nt >> 1] + (nt & 1) * 2);
        }
    }

    // ======== fused GN epilogue ========
    float2 bvw[8];
#pragma unroll
    for (int nt = 0; nt < 8; nt++) {
        int cc = n0 + wn * 64 + nt * 8 + acol * 2;
        bvw[nt] = *(const float2*)&bias_w[cc];
    }
#pragma unroll
    for (int mt = 0; mt < 4; mt++) {
        int rl = wm * 64 + mt * 16 + arow;
        size_t r0 = (size_t)m0 + rl;
        float mu0 = stat[rl * 2],       rs0 = stat[rl * 2 + 1];
        float mu1 = stat[(rl + 8) * 2], rs1 = stat[(rl + 8) * 2 + 1];
#pragma unroll
        for (int nt = 0; nt < 8; nt++) {
            int ccl = wn * 64 + nt * 8 + acol * 2;
            int cc = n0 + ccl;
            float w00 = acc[mt][nt][0] + bvw[nt].x;
            float w01 = acc[mt][nt][1] + bvw[nt].y;
            float w10 = acc[mt][nt][2] + bvw[nt].x;
            float w11 = acc[mt][nt][3] + bvw[nt].y;
            float2 b0 = __half22float2(bsave[rl * 64 + (ccl >> 1)]);
            float2 b1 = __half22float2(bsave[(rl + 8) * 64 + (ccl >> 1)]);
            float2 x0 = __half22float2(*(__half2*)&x[r0 * H + cc]);
            float2 x1 = __half22float2(*(__half2*)&x[(r0 + 8) * H + cc]);
            float y00 = fmaxf((x0.x - mu0) * rs0 * w00 + b0.x, 0.0f);
            float y01 = fmaxf((x0.y - mu0) * rs0 * w01 + b0.y, 0.0f);
            float y10 = fmaxf((x1.x - mu1) * rs1 * w10 + b1.x, 0.0f);
            float y11 = fmaxf((x1.y - mu1) * rs1 * w11 + b1.y, 0.0f);
            *(__half2*)&x[r0 * H + cc] = __floats2half2_rn(y00, y01);
            *(__half2*)&x[(r0 + 8) * H + cc] = __floats2half2_rn(y10, y11);
        }
    }
}

// ---------------------------------------------------------------------------
// Weight transpose + fp16 convert: src fp32 [K, N] -> dst fp16 [N, K]
// ---------------------------------------------------------------------------
__global__ void transpose_k(const float* __restrict__ src, __half* __restrict__ dst,
                            int K, int N)
{
    __shared__ float t[32][33];
    int x = blockIdx.x * 32 + threadIdx.x;
    int y0 = blockIdx.y * 32;
#pragma unroll
    for (int j = 0; j < 32; j += 8)
        t[threadIdx.y + j][threadIdx.x] = src[(size_t)(y0 + threadIdx.y + j) * N + x];
    __syncthreads();
    int x2 = y0 + threadIdx.x;
    int y2 = blockIdx.x * 32 + threadIdx.y;
#pragma unroll
    for (int j = 0; j < 32; j += 8)
        dst[(size_t)(y2 + j) * K + x2] = __float2half_rn(t[threadIdx.x][threadIdx.y + j]);
}

// ---------------------------------------------------------------------------
// Elementwise fp32 -> fp16 (x_feature)
// ---------------------------------------------------------------------------
__global__ __launch_bounds__(256) void cvt_h_vec(
    const float* __restrict__ in, __half* __restrict__ out, size_t n4)
{
    size_t i = (size_t)blockIdx.x * blockDim.x + threadIdx.x;
    if (i >= n4) return;
    float4 v = ((const float4*)in)[i];
    ((__half2*)out)[i * 2] = __floats2half2_rn(v.x, v.y);
    ((__half2*)out)[i * 2 + 1] = __floats2half2_rn(v.z, v.w);
}

// ---------------------------------------------------------------------------
// Hypernet hidden: H = fp16(relu(P @ W + b)), P:[B,8], W:[8,32]
// ---------------------------------------------------------------------------
__global__ __launch_bounds__(256) void hyper_hidden(
    const float* __restrict__ P, const float* __restrict__ W,
    const float* __restrict__ bias, __half* __restrict__ H, int B)
{
    int idx = blockIdx.x * blockDim.x + threadIdx.x;
    int row = idx >> 5;
    int j = idx & 31;
    if (row >= B) return;
    float s = bias[j];
#pragma unroll
    for (int k = 0; k < PDIM; k++)
        s += P[row * PDIM + k] * W[k * 32 + j];
    H[(size_t)row * 32 + j] = __float2half_rn(fmaxf(s, 0.0f));
}

// ---------------------------------------------------------------------------
// log_softmax over 256 columns, one row per block (256 threads).
// ---------------------------------------------------------------------------
__device__ __forceinline__ float warpReduceSum(float v)
{
#pragma unroll
    for (int o = 16; o > 0; o >>= 1) v += __shfl_xor_sync(0xffffffffu, v, o);
    return v;
}

__global__ __launch_bounds__(256) void logsoftmax256(
    const float* __restrict__ x, float* __restrict__ out)
{
    const int row = blockIdx.x;
    const int tid = threadIdx.x;
    const size_t base = (size_t)row * 256;
    float v = x[base + tid];

    __shared__ float shm[8];
    __shared__ float shs[8];

    float m = v;
#pragma unroll
    for (int o = 16; o > 0; o >>= 1) m = fmaxf(m, __shfl_xor_sync(0xffffffffu, m, o));
    if ((tid & 31) == 0) shm[tid >> 5] = m;
    __syncthreads();
    float mx = shm[0];
#pragma unroll
    for (int i = 1; i < 8; i++) mx = fmaxf(mx, shm[i]);

    float e = expf(v - mx);
    float se = warpReduceSum(e);
    if ((tid & 31) == 0) shs[tid >> 5] = se;
    __syncthreads();
    float tot = 0.0f;
#pragma unroll
    for (int i = 0; i < 8; i++) tot += shs[i];

    out[base + tid] = (v - mx) - logf(tot);
}

// ---------------------------------------------------------------------------
// kernel_launch
// ---------------------------------------------------------------------------
extern "C" void kernel_launch(void* const* d_in, const int* in_sizes, int n_in,
                              void* d_out, int out_size)
{
    const float* x_feature = (const float*)d_in[0];
    const float* x_param   = (const float*)d_in[1];
    const float* hw1_1_w   = (const float*)d_in[2];
    const float* hw1_1_b   = (const float*)d_in[3];
    const float* hw1_2_w   = (const float*)d_in[4];
    const float* hw1_2_b   = (const float*)d_in[5];
    const float* hb1_1_w   = (const float*)d_in[6];
    const float* hb1_1_b   = (const float*)d_in[7];
    const float* hb1_2_w   = (const float*)d_in[8];
    const float* hb1_2_b   = (const float*)d_in[9];
    const float* hw2_1_w   = (const float*)d_in[10];
    const float* hw2_1_b   = (const float*)d_in[11];
    const float* hw2_2_w   = (const float*)d_in[12];
    const float* hw2_2_b   = (const float*)d_in[13];
    const float* hb2_1_w   = (const float*)d_in[14];
    const float* hb2_1_b   = (const float*)d_in[15];
    const float* hb2_2_w   = (const float*)d_in[16];
    const float* hb2_2_b   = (const float*)d_in[17];
    const float* l1_w      = (const float*)d_in[18];
    const float* l1_b      = (const float*)d_in[19];
    const float* l2_w      = (const float*)d_in[20];
    const float* l2_b      = (const float*)d_in[21];
    const float* l3_w      = (const float*)d_in[22];
    const float* l3_b      = (const float*)d_in[23];

    const int B = in_sizes[0] / CIN;   // 32768

    __half *p_h1, *p_h2, *p_h3, *p_h4, *p_xfh, *p_x1h, *p_x2h;
    __half *p_l1wt, *p_l2wt, *p_l3wt, *p_hw12t, *p_hb12t, *p_hw22t, *p_hb22t;
    float *p_x3, *p_stats;
    cudaGetSymbolAddress((void**)&p_h1, g_h1);
    cudaGetSymbolAddress((void**)&p_h2, g_h2);
    cudaGetSymbolAddress((void**)&p_h3, g_h3);
    cudaGetSymbolAddress((void**)&p_h4, g_h4);
    cudaGetSymbolAddress((void**)&p_xfh, g_xfh);
    cudaGetSymbolAddress((void**)&p_x1h, g_x1h);
    cudaGetSymbolAddress((void**)&p_x2h, g_x2h);
    cudaGetSymbolAddress((void**)&p_x3, g_x3);
    cudaGetSymbolAddress((void**)&p_stats, g_stats);
    cudaGetSymbolAddress((void**)&p_l1wt, g_l1wt);
    cudaGetSymbolAddress((void**)&p_l2wt, g_l2wt);
    cudaGetSymbolAddress((void**)&p_l3wt, g_l3wt);
    cudaGetSymbolAddress((void**)&p_hw12t, g_hw12t);
    cudaGetSymbolAddress((void**)&p_hb12t, g_hb12t);
    cudaGetSymbolAddress((void**)&p_hw22t, g_hw22t);
    cudaGetSymbolAddress((void**)&p_hb22t, g_hb22t);

    float* ssum1 = p_stats;
    float* ssq1  = p_stats + B_MAX;
    float* ssum2 = p_stats + 2 * B_MAX;
    float* ssq2  = p_stats + 3 * B_MAX;

    constexpr int SMEM64 = 2 * 256 * (64 + 8) * 2;        // 73728
    constexpr int SMEM_FUSED = 4 * 128 * 40 * 2 + 128 * 128 * 2;  // 40960+32768=73728
    cudaFuncSetAttribute((const void*)gemm_h<__half>, cudaFuncAttributeMaxDynamicSharedMemorySize, SMEM64);
    cudaFuncSetAttribute((const void*)gemm_h<float>,  cudaFuncAttributeMaxDynamicSharedMemorySize, SMEM64);
    cudaFuncSetAttribute((const void*)hyper_gn_fused, cudaFuncAttributeMaxDynamicSharedMemorySize, SMEM_FUSED);

    dim3 tb(32, 8);
    const int mg = B / 128;
    int hblocks = (B * 32 + 255) / 256;

    // zero GN stat accumulators (graph-capturable async memset)
    cudaMemsetAsync(p_stats, 0, 4 * (size_t)B_MAX * sizeof(float), 0);

    transpose_k<<<dim3(H1 / 32, CIN / 32), tb>>>(l1_w, p_l1wt, CIN, H1);
    {
        size_t n4 = (size_t)B * CIN / 4;
        cvt_h_vec<<<(unsigned)((n4 + 255) / 256), 256>>>(x_feature, p_xfh, n4);
    }
    hyper_hidden<<<hblocks, 256>>>(x_param, hw1_1_w, hw1_1_b, p_h1, B);

    // l1 big GEMM (+row stats)
    gemm_h<__half><<<dim3(H1 / 128, mg), 128, SMEM64>>>(
        B, H1, CIN, p_xfh, p_l1wt, l1_b, p_x1h, ssum1, ssq1);

    transpose_k<<<dim3(H2 / 32, H1 / 32), tb>>>(l2_w, p_l2wt, H1, H2);
    transpose_k<<<dim3(COUT / 32, H2 / 32), tb>>>(l3_w, p_l3wt, H2, COUT);
    hyper_hidden<<<hblocks, 256>>>(x_param, hb1_1_w, hb1_1_b, p_h2, B);
    hyper_hidden<<<hblocks, 256>>>(x_param, hw2_1_w, hw2_1_b, p_h3, B);
    hyper_hidden<<<hblocks, 256>>>(x_param, hb2_1_w, hb2_1_b, p_h4, B);
    transpose_k<<<dim3(H1 / 32, 1), tb>>>(hw1_2_w, p_hw12t, 32, H1);
    transpose_k<<<dim3(H1 / 32, 1), tb>>>(hb1_2_w, p_hb12t, 32, H1);
    transpose_k<<<dim3(H2 / 32, 1), tb>>>(hw2_2_w, p_hw22t, 32, H2);
    transpose_k<<<dim3(H2 / 32, 1), tb>>>(hb2_2_w, p_hb22t, 32, H2);

    // layer 1: fully fused hypernet-output (w & b) + groupnorm, in place on x1h
    hyper_gn_fused<<<dim3(H1 / 128, mg), 128, SMEM_FUSED>>>(
        B, H1, p_h1, p_h2, p_hw12t, p_hb12t, hw1_2_b, hb1_2_b, ssum1, ssq1, p_x1h);

    // l2 big GEMM (+row stats)
    gemm_h<__half><<<dim3(H2 / 128, mg), 128, SMEM64>>>(
        B, H2, H1, p_x1h, p_l2wt, l2_b, p_x2h, ssum2, ssq2);

    // layer 2: fully fused
    hyper_gn_fused<<<dim3(H2 / 128, mg), 128, SMEM_FUSED>>>(
        B, H2, p_h3, p_h4, p_hw22t, p_hb22t, hw2_2_b, hb2_2_b, ssum2, ssq2, p_x2h);

    // l3 GEMM -> fp32 x3 (no stats)
    gemm_h<float><<<dim3(COUT / 128, mg), 128, SMEM64>>>(
        B, COUT, H2, p_x2h, p_l3wt, l3_b, p_x3, nullptr, nullptr);

    // log_softmax -> output
    logsoftmax256<<<B, 256>>>(p_x3, (float*)d_out);
}

// round 17
// speedup vs baseline: 1.0335x; 1.0335x over previous
#include <cuda_runtime.h>
#include <cuda_fp16.h>
#include <cstdint>
#include <math.h>

// ---------------------------------------------------------------------------
// Problem dims (fixed by the dataset)
// ---------------------------------------------------------------------------
#define B_MAX   32768
#define CIN     512
#define H1      2048
#define H2      1024
#define COUT    256
#define PDIM    8

// ---------------------------------------------------------------------------
// Scratch (__device__ globals: the sanctioned no-alloc workaround)
// ---------------------------------------------------------------------------
__device__ __half g_h1[B_MAX * 32];
__device__ __half g_h2[B_MAX * 32];
__device__ __half g_h3[B_MAX * 32];
__device__ __half g_h4[B_MAX * 32];
__device__ __half g_xfh[(size_t)B_MAX * CIN];
__device__ __half g_x1h[(size_t)B_MAX * H1];
__device__ __half g_x2h[(size_t)B_MAX * H2];
__device__ __half g_b1h[(size_t)B_MAX * H1];
__device__ __half g_b2h[(size_t)B_MAX * H2];
__device__ float  g_x3[(size_t)B_MAX * COUT];
__device__ float  g_stats[4 * B_MAX];          // ssum1, ssq1, ssum2, ssq2
// transposed fp16 weights [N, K]
__device__ __half g_l1wt[(size_t)H1 * CIN];
__device__ __half g_l2wt[(size_t)H2 * H1];
__device__ __half g_l3wt[(size_t)COUT * H2];
__device__ __half g_hw12t[H1 * 32];
__device__ __half g_hb12t[H1 * 32];
__device__ __half g_hw22t[H2 * 32];
__device__ __half g_hb22t[H2 * 32];

// ---------------------------------------------------------------------------
// Helpers (all architecture-portable PTX: sm_80+)
// ---------------------------------------------------------------------------
__device__ __forceinline__ uint32_t smem_u32(const void* p)
{
    uint32_t a;
    asm("{ .reg .u64 t; cvta.to.shared.u64 t, %1; cvt.u32.u64 %0, t; }"
        : "=r"(a) : "l"(p));
    return a;
}

__device__ __forceinline__ void cp_async16(uint32_t dst, const void* src)
{
    asm volatile("cp.async.cg.shared.global [%0], [%1], 16;"
                 :: "r"(dst), "l"(src));
}
__device__ __forceinline__ void cp_commit()
{
    asm volatile("cp.async.commit_group;" ::: "memory");
}
template <int N>
__device__ __forceinline__ void cp_wait()
{
    asm volatile("cp.async.wait_group %0;" :: "n"(N) : "memory");
}

// fp16 m16n8k16 mma, fp32 accumulate (portable since sm_80)
__device__ __forceinline__ void mma16(float* d, const uint32_t* a, const uint32_t* b)
{
    asm volatile(
        "mma.sync.aligned.m16n8k16.row.col.f32.f16.f16.f32 "
        "{%0,%1,%2,%3}, {%4,%5,%6,%7}, {%8,%9}, {%0,%1,%2,%3};"
        : "+f"(d[0]), "+f"(d[1]), "+f"(d[2]), "+f"(d[3])
        : "r"(a[0]), "r"(a[1]), "r"(a[2]), "r"(a[3]), "r"(b[0]), "r"(b[1]));
}

__device__ __forceinline__ void ldsm4(uint32_t* r, uint32_t addr)
{
    asm volatile("ldmatrix.sync.aligned.m8n8.x4.shared.b16 {%0,%1,%2,%3}, [%4];"
                 : "=r"(r[0]), "=r"(r[1]), "=r"(r[2]), "=r"(r[3]) : "r"(addr));
}

// ---------------------------------------------------------------------------
// fp16 tensor-core GEMM (champion config):  C = A @ Bt^T + bias
// BM=BN=128, BK=64; 128 threads = 4 warps (2x2), 64x64 per warp.
// 2-stage double buffer. Optional per-row sum/sumsq accumulation (for GN).
// ---------------------------------------------------------------------------
template <typename OutT>
__global__ __launch_bounds__(128, 2) void gemm_h(
    int M, int N, int K,
    const __half* __restrict__ A, const __half* __restrict__ Bt,
    const float* __restrict__ bias, OutT* __restrict__ C,
    float* __restrict__ ssum, float* __restrict__ ssq)
{
    constexpr int BKH = 64;
    constexpr int LDH = BKH + 8;
    constexpr int A_H = 128 * LDH;
    constexpr int STAGE_H = 256 * LDH;
    constexpr int CPR = BKH / 8;
    constexpr int KS = BKH / 16;

    extern __shared__ __half smh[];          // [2][STAGE_H]

    const int tid = threadIdx.x;
    const int lane = tid & 31, wid = tid >> 5;
    const int wm = wid & 1, wn = wid >> 1;
    const int m0 = blockIdx.y * 128;
    const int n0 = blockIdx.x * 128;
    const int nkt = K / BKH;

    const __half* Ag = A + (size_t)m0 * K;
    const __half* Bg = Bt + (size_t)n0 * K;
    const uint32_t sS = smem_u32(smh);

    const uint32_t a_off =
        (uint32_t)(((wm * 64 + (lane & 15)) * LDH + ((lane >> 4) << 3)) * 2);
    const uint32_t b_off =
        (uint32_t)(((wn * 64 + ((lane >> 4) << 3) + (lane & 7)) * LDH +
                    (((lane >> 3) & 1) << 3)) * 2);

    float acc[4][8][4];
#pragma unroll
    for (int mt = 0; mt < 4; mt++)
#pragma unroll
        for (int nt = 0; nt < 8; nt++)
#pragma unroll
            for (int j = 0; j < 4; j++) acc[mt][nt][j] = 0.0f;

    auto load_tiles = [&](int t) {
        const uint32_t base = sS + (uint32_t)((t & 1) * (STAGE_H * 2));
        const __half* ga = Ag + t * BKH;
        const __half* gb = Bg + t * BKH;
#pragma unroll
        for (int it = 0; it < CPR; it++) {
            int idx = tid + it * 128;
            int r = idx / CPR, cc = idx % CPR;
            uint32_t off = r * (LDH * 2) + cc * 16;
            cp_async16(base + off, ga + (size_t)r * K + cc * 8);
            cp_async16(base + A_H * 2 + off, gb + (size_t)r * K + cc * 8);
        }
    };

    load_tiles(0);
    cp_commit();

    for (int i = 0; i < nkt; i++) {
        if (i + 1 < nkt) {
            load_tiles(i + 1);
            cp_commit();
            cp_wait<1>();
        } else {
            cp_wait<0>();
        }
        __syncthreads();

        const uint32_t st = sS + (uint32_t)((i & 1) * (STAGE_H * 2));
        const uint32_t sa = st + a_off;
        const uint32_t sb = st + (uint32_t)(A_H * 2) + b_off;

#pragma unroll
        for (int ks = 0; ks < KS; ks++) {
            uint32_t af[4][4], bf[4][4];
#pragma unroll
            for (int mt = 0; mt < 4; mt++)
                ldsm4(af[mt], sa + (uint32_t)((mt * 16 * LDH + ks * 16) * 2));
#pragma unroll
            for (int np = 0; np < 4; np++)
                ldsm4(bf[np], sb + (uint32_t)((np * 16 * LDH + ks * 16) * 2));
#pragma unroll
            for (int mt = 0; mt < 4; mt++)
#pragma unroll
                for (int nt = 0; nt < 8; nt++)
                    mma16(acc[mt][nt], af[mt], bf[nt >> 1] + (nt & 1) * 2);
        }
        __syncthreads();
    }

    // ---- epilogue: bias + store (+ optional per-row stats via atomics) ----
    const int arow = lane >> 2;
    const int acol = lane & 3;
    float2 bv[8];
#pragma unroll
    for (int nt = 0; nt < 8; nt++) {
        int cc = n0 + wn * 64 + nt * 8 + acol * 2;
        bv[nt] = *(const float2*)&bias[cc];
    }
#pragma unroll
    for (int mt = 0; mt < 4; mt++) {
        size_t r0 = (size_t)m0 + wm * 64 + mt * 16 + arow;
        float s0 = 0.0f, q0 = 0.0f, s1 = 0.0f, q1 = 0.0f;
#pragma unroll
        for (int nt = 0; nt < 8; nt++) {
            int cc = n0 + wn * 64 + nt * 8 + acol * 2;
            float v00 = acc[mt][nt][0] + bv[nt].x;
            float v01 = acc[mt][nt][1] + bv[nt].y;
            float v10 = acc[mt][nt][2] + bv[nt].x;
            float v11 = acc[mt][nt][3] + bv[nt].y;
            s0 += v00 + v01; q0 += v00 * v00 + v01 * v01;
            s1 += v10 + v11; q1 += v10 * v10 + v11 * v11;
            if constexpr (sizeof(OutT) == 2) {
                *(__half2*)&C[r0 * N + cc] = __floats2half2_rn(v00, v01);
                *(__half2*)&C[(r0 + 8) * N + cc] = __floats2half2_rn(v10, v11);
            } else {
                float2 a0 = { v00, v01 }, a1 = { v10, v11 };
                *(float2*)&C[r0 * N + cc] = a0;
                *(float2*)&C[(r0 + 8) * N + cc] = a1;
            }
        }
        if (ssum != nullptr) {
#pragma unroll
            for (int o = 1; o <= 2; o <<= 1) {
                s0 += __shfl_xor_sync(0xffffffffu, s0, o);
                q0 += __shfl_xor_sync(0xffffffffu, q0, o);
                s1 += __shfl_xor_sync(0xffffffffu, s1, o);
                q1 += __shfl_xor_sync(0xffffffffu, q1, o);
            }
            if (acol == 0) {
                atomicAdd(&ssum[r0], s0);
                atomicAdd(&ssq[r0], q0);
                atomicAdd(&ssum[r0 + 8], s1);
                atomicAdd(&ssq[r0 + 8], q1);
            }
        }
    }
}

// ---------------------------------------------------------------------------
// K=32 hypernet GEMM (materializes b): C = A @ Bt^T + bias, fp16 out.
// ---------------------------------------------------------------------------
__global__ __launch_bounds__(128, 2) void gemm_hyp(
    int M, int N,
    const __half* __restrict__ A, const __half* __restrict__ Bt,
    const float* __restrict__ bias, __half* __restrict__ C)
{
    constexpr int K = 32;
    constexpr int LDH = 40;
    constexpr int A_H = 128 * LDH;

    __shared__ __half smh[256 * LDH];

    const int tid = threadIdx.x;
    const int lane = tid & 31, wid = tid >> 5;
    const int wm = wid & 1, wn = wid >> 1;
    const int m0 = blockIdx.y * 128;
    const int n0 = blockIdx.x * 128;

    const __half* Ag = A + (size_t)m0 * K;
    const __half* Bg = Bt + (size_t)n0 * K;
    const uint32_t sS = smem_u32(smh);

#pragma unroll
    for (int it = 0; it < 4; it++) {
        int idx = tid + it * 128;
        int r = idx >> 2, cc = idx & 3;
        uint32_t off = r * (LDH * 2) + cc * 16;
        cp_async16(sS + off, Ag + (size_t)r * K + cc * 8);
        cp_async16(sS + A_H * 2 + off, Bg + (size_t)r * K + cc * 8);
    }
    cp_commit();

    const uint32_t a_off =
        (uint32_t)(((wm * 64 + (lane & 15)) * LDH + ((lane >> 4) << 3)) * 2);
    const uint32_t b_off =
        (uint32_t)(((wn * 64 + ((lane >> 4) << 3) + (lane & 7)) * LDH +
                    (((lane >> 3) & 1) << 3)) * 2);

    float acc[4][8][4];
#pragma unroll
    for (int mt = 0; mt < 4; mt++)
#pragma unroll
        for (int nt = 0; nt < 8; nt++)
#pragma unroll
            for (int j = 0; j < 4; j++) acc[mt][nt][j] = 0.0f;

    cp_wait<0>();
    __syncthreads();

    const uint32_t sa = sS + a_off;
    const uint32_t sb = sS + (uint32_t)(A_H * 2) + b_off;

#pragma unroll
    for (int ks = 0; ks < 2; ks++) {
        uint32_t af[4][4], bf[4][4];
#pragma unroll
        for (int mt = 0; mt < 4; mt++)
            ldsm4(af[mt], sa + (uint32_t)((mt * 16 * LDH + ks * 16) * 2));
#pragma unroll
        for (int np = 0; np < 4; np++)
            ldsm4(bf[np], sb + (uint32_t)((np * 16 * LDH + ks * 16) * 2));
#pragma unroll
        for (int mt = 0; mt < 4; mt++)
#pragma unroll
            for (int nt = 0; nt < 8; nt++)
                mma16(acc[mt][nt], af[mt], bf[nt >> 1] + (nt & 1) * 2);
    }

    const int arow = lane >> 2;
    const int acol = lane & 3;
    float2 bv[8];
#pragma unroll
    for (int nt = 0; nt < 8; nt++) {
        int cc = n0 + wn * 64 + nt * 8 + acol * 2;
        bv[nt] = *(const float2*)&bias[cc];
    }
#pragma unroll
    for (int mt = 0; mt < 4; mt++) {
        size_t r0 = (size_t)m0 + wm * 64 + mt * 16 + arow;
#pragma unroll
        for (int nt = 0; nt < 8; nt++) {
            int cc = n0 + wn * 64 + nt * 8 + acol * 2;
            *(__half2*)&C[r0 * N + cc] =
                __floats2half2_rn(acc[mt][nt][0] + bv[nt].x, acc[mt][nt][1] + bv[nt].y);
            *(__half2*)&C[(r0 + 8) * N + cc] =
                __floats2half2_rn(acc[mt][nt][2] + bv[nt].x, acc[mt][nt][3] + bv[nt].y);
        }
    }
}

// ---------------------------------------------------------------------------
// K=32 w-GEMM with fused groupnorm epilogue (validated R15):
//   w = A @ Wt^T + bias_w ; x = relu((x-mu)*rstd*w + b) in place.
// ---------------------------------------------------------------------------
__global__ __launch_bounds__(128, 2) void gemm_hyp_gn(
    int M, int H,
    const __half* __restrict__ A, const __half* __restrict__ Bt,
    const float* __restrict__ bias,
    const float* __restrict__ ssum, const float* __restrict__ ssq,
    const __half* __restrict__ bh, __half* x)
{
    constexpr int K = 32;
    constexpr int LDH = 40;
    constexpr int A_H = 128 * LDH;

    __shared__ __half smh[256 * LDH];
    __shared__ float stat[256];

    const int tid = threadIdx.x;
    const int lane = tid & 31, wid = tid >> 5;
    const int wm = wid & 1, wn = wid >> 1;
    const int m0 = blockIdx.y * 128;
    const int n0 = blockIdx.x * 128;

    const __half* Ag = A + (size_t)m0 * K;
    const __half* Bg = Bt + (size_t)n0 * K;
    const uint32_t sS = smem_u32(smh);

#pragma unroll
    for (int it = 0; it < 4; it++) {
        int idx = tid + it * 128;
        int r = idx >> 2, cc = idx & 3;
        uint32_t off = r * (LDH * 2) + cc * 16;
        cp_async16(sS + off, Ag + (size_t)r * K + cc * 8);
        cp_async16(sS + A_H * 2 + off, Bg + (size_t)r * K + cc * 8);
    }
    cp_commit();

    {
        float invH = 1.0f / (float)H;
        int r = m0 + tid;
        float mu = ssum[r] * invH;
        float var = ssq[r] * invH - mu * mu;
        stat[tid * 2] = mu;
        stat[tid * 2 + 1] = rsqrtf(var + 1e-5f);
    }

    const uint32_t a_off =
        (uint32_t)(((wm * 64 + (lane & 15)) * LDH + ((lane >> 4) << 3)) * 2);
    const uint32_t b_off =
        (uint32_t)(((wn * 64 + ((lane >> 4) << 3) + (lane & 7)) * LDH +
                    (((lane >> 3) & 1) << 3)) * 2);

    float acc[4][8][4];
#pragma unroll
    for (int mt = 0; mt < 4; mt++)
#pragma unroll
        for (int nt = 0; nt < 8; nt++)
#pragma unroll
            for (int j = 0; j < 4; j++) acc[mt][nt][j] = 0.0f;

    cp_wait<0>();
    __syncthreads();

    const uint32_t sa = sS + a_off;
    const uint32_t sb = sS + (uint32_t)(A_H * 2) + b_off;

#pragma unroll
    for (int ks = 0; ks < 2; ks++) {
        uint32_t af[4][4], bf[4][4];
#pragma unroll
        for (int mt = 0; mt < 4; mt++)
            ldsm4(af[mt], sa + (uint32_t)((mt * 16 * LDH + ks * 16) * 2));
#pragma unroll
        for (int np = 0; np < 4; np++)
            ldsm4(bf[np], sb + (uint32_t)((np * 16 * LDH + ks * 16) * 2));
#pragma unroll
        for (int mt = 0; mt < 4; mt++)
#pragma unroll
            for (int nt = 0; nt < 8; nt++)
                mma16(acc[mt][nt], af[mt], bf[nt >> 1] + (nt & 1) * 2);
    }

    const int arow = lane >> 2;
    const int acol = lane & 3;
    float2 bv[8];
#pragma unroll
    for (int nt = 0; nt < 8; nt++) {
        int cc = n0 + wn * 64 + nt * 8 + acol * 2;
        bv[nt] = *(const float2*)&bias[cc];
    }
#pragma unroll
    for (int mt = 0; mt < 4; mt++) {
        int rl = wm * 64 + mt * 16 + arow;
        size_t r0 = (size_t)m0 + rl;
        float mu0 = stat[rl * 2],       rs0 = stat[rl * 2 + 1];
        float mu1 = stat[(rl + 8) * 2], rs1 = stat[(rl + 8) * 2 + 1];
#pragma unroll
        for (int nt = 0; nt < 8; nt++) {
            int cc = n0 + wn * 64 + nt * 8 + acol * 2;
            float w00 = acc[mt][nt][0] + bv[nt].x;
            float w01 = acc[mt][nt][1] + bv[nt].y;
            float w10 = acc[mt][nt][2] + bv[nt].x;
            float w11 = acc[mt][nt][3] + bv[nt].y;
            float2 b0 = __half22float2(*(const __half2*)&bh[r0 * H + cc]);
            float2 b1 = __half22float2(*(const __half2*)&bh[(r0 + 8) * H + cc]);
            float2 x0 = __half22float2(*(__half2*)&x[r0 * H + cc]);
            float2 x1 = __half22float2(*(__half2*)&x[(r0 + 8) * H + cc]);
            float y00 = fmaxf((x0.x - mu0) * rs0 * w00 + b0.x, 0.0f);
            float y01 = fmaxf((x0.y - mu0) * rs0 * w01 + b0.y, 0.0f);
            float y10 = fmaxf((x1.x - mu1) * rs1 * w10 + b1.x, 0.0f);
            float y11 = fmaxf((x1.y - mu1) * rs1 * w11 + b1.y, 0.0f);
            *(__half2*)&x[r0 * H + cc] = __floats2half2_rn(y00, y01);
            *(__half2*)&x[(r0 + 8) * H + cc] = __floats2half2_rn(y10, y11);
        }
    }
}

// ---------------------------------------------------------------------------
// Weight transpose + fp16 convert: src fp32 [K, N] -> dst fp16 [N, K]
// ---------------------------------------------------------------------------
__global__ void transpose_k(const float* __restrict__ src, __half* __restrict__ dst,
                            int K, int N)
{
    __shared__ float t[32][33];
    int x = blockIdx.x * 32 + threadIdx.x;
    int y0 = blockIdx.y * 32;
#pragma unroll
    for (int j = 0; j < 32; j += 8)
        t[threadIdx.y + j][threadIdx.x] = src[(size_t)(y0 + threadIdx.y + j) * N + x];
    __syncthreads();
    int x2 = y0 + threadIdx.x;
    int y2 = blockIdx.x * 32 + threadIdx.y;
#pragma unroll
    for (int j = 0; j < 32; j += 8)
        dst[(size_t)(y2 + j) * K + x2] = __float2half_rn(t[threadIdx.x][threadIdx.y + j]);
}

// Batched variant for the 4 K=32 hypernet weight transposes (z selects set).
__global__ void transpose4(
    const float* __restrict__ s0, __half* __restrict__ d0, int n0_,
    const float* __restrict__ s1, __half* __restrict__ d1, int n1_,
    const float* __restrict__ s2, __half* __restrict__ d2, int n2_,
    const float* __restrict__ s3, __half* __restrict__ d3, int n3_)
{
    int z = blockIdx.z;
    const float* src = z == 0 ? s0 : z == 1 ? s1 : z == 2 ? s2 : s3;
    __half* dst = z == 0 ? d0 : z == 1 ? d1 : z == 2 ? d2 : d3;
    int N = z == 0 ? n0_ : z == 1 ? n1_ : z == 2 ? n2_ : n3_;
    if ((int)(blockIdx.x * 32) >= N) return;

    __shared__ float t[32][33];
    int x = blockIdx.x * 32 + threadIdx.x;
#pragma unroll
    for (int j = 0; j < 32; j += 8)
        t[threadIdx.y + j][threadIdx.x] = src[(size_t)(threadIdx.y + j) * N + x];
    __syncthreads();
    int x2 = threadIdx.x;
    int y2 = blockIdx.x * 32 + threadIdx.y;
#pragma unroll
    for (int j = 0; j < 32; j += 8)
        dst[(size_t)(y2 + j) * 32 + x2] = __float2half_rn(t[threadIdx.x][threadIdx.y + j]);
}

// ---------------------------------------------------------------------------
// Elementwise fp32 -> fp16 (x_feature)
// ---------------------------------------------------------------------------
__global__ __launch_bounds__(256) void cvt_h_vec(
    const float* __restrict__ in, __half* __restrict__ out, size_t n4)
{
    size_t i = (size_t)blockIdx.x * blockDim.x + threadIdx.x;
    if (i >= n4) return;
    float4 v = ((const float4*)in)[i];
    ((__half2*)out)[i * 2] = __floats2half2_rn(v.x, v.y);
    ((__half2*)out)[i * 2 + 1] = __floats2half2_rn(v.z, v.w);
}

// ---------------------------------------------------------------------------
// All 4 hypernet hidden layers in one launch (validated R9/R12):
// H = fp16(relu(P @ W + b)), P:[B,8], W:[8,32]
// ---------------------------------------------------------------------------
__global__ __launch_bounds__(256) void hyper_hidden4(
    const float* __restrict__ P,
    const float* __restrict__ W0, const float* __restrict__ c0, __half* __restrict__ H0,
    const float* __restrict__ W1, const float* __restrict__ c1, __half* __restrict__ Hh1,
    const float* __restrict__ W2, const float* __restrict__ c2, __half* __restrict__ Hh2,
    const float* __restrict__ W3, const float* __restrict__ c3, __half* __restrict__ Hh3,
    int B)
{
    int set = blockIdx.y;
    const float* W = set == 0 ? W0 : set == 1 ? W1 : set == 2 ? W2 : W3;
    const float* c = set == 0 ? c0 : set == 1 ? c1 : set == 2 ? c2 : c3;
    __half* H = set == 0 ? H0 : set == 1 ? Hh1 : set == 2 ? Hh2 : Hh3;

    int idx = blockIdx.x * blockDim.x + threadIdx.x;
    int row = idx >> 5;
    int j = idx & 31;
    if (row >= B) return;
    float s = c[j];
#pragma unroll
    for (int k = 0; k < PDIM; k++)
        s += P[row * PDIM + k] * W[k * 32 + j];
    H[(size_t)row * 32 + j] = __float2half_rn(fmaxf(s, 0.0f));
}

// ---------------------------------------------------------------------------
// log_softmax over 256 columns, one row per block (256 threads).
// ---------------------------------------------------------------------------
__device__ __forceinline__ float warpReduceSum(float v)
{
#pragma unroll
    for (int o = 16; o > 0; o >>= 1) v += __shfl_xor_sync(0xffffffffu, v, o);
    return v;
}

__global__ __launch_bounds__(256) void logsoftmax256(
    const float* __restrict__ x, float* __restrict__ out)
{
    const int row = blockIdx.x;
    const int tid = threadIdx.x;
    const size_t base = (size_t)row * 256;
    float v = x[base + tid];

    __shared__ float shm[8];
    __shared__ float shs[8];

    float m = v;
#pragma unroll
    for (int o = 16; o > 0; o >>= 1) m = fmaxf(m, __shfl_xor_sync(0xffffffffu, m, o));
    if ((tid & 31) == 0) shm[tid >> 5] = m;
    __syncthreads();
    float mx = shm[0];
#pragma unroll
    for (int i = 1; i < 8; i++) mx = fmaxf(mx, shm[i]);

    float e = expf(v - mx);
    float se = warpReduceSum(e);
    if ((tid & 31) == 0) shs[tid >> 5] = se;
    __syncthreads();
    float tot = 0.0f;
#pragma unroll
    for (int i = 0; i < 8; i++) tot += shs[i];

    out[base + tid] = (v - mx) - logf(tot);
}

// ---------------------------------------------------------------------------
// kernel_launch — R15 structure + consolidated small launches.
// ---------------------------------------------------------------------------
extern "C" void kernel_launch(void* const* d_in, const int* in_sizes, int n_in,
                              void* d_out, int out_size)
{
    const float* x_feature = (const float*)d_in[0];
    const float* x_param   = (const float*)d_in[1];
    const float* hw1_1_w   = (const float*)d_in[2];
    const float* hw1_1_b   = (const float*)d_in[3];
    const float* hw1_2_w   = (const float*)d_in[4];
    const float* hw1_2_b   = (const float*)d_in[5];
    const float* hb1_1_w   = (const float*)d_in[6];
    const float* hb1_1_b   = (const float*)d_in[7];
    const float* hb1_2_w   = (const float*)d_in[8];
    const float* hb1_2_b   = (const float*)d_in[9];
    const float* hw2_1_w   = (const float*)d_in[10];
    const float* hw2_1_b   = (const float*)d_in[11];
    const float* hw2_2_w   = (const float*)d_in[12];
    const float* hw2_2_b   = (const float*)d_in[13];
    const float* hb2_1_w   = (const float*)d_in[14];
    const float* hb2_1_b   = (const float*)d_in[15];
    const float* hb2_2_w   = (const float*)d_in[16];
    const float* hb2_2_b   = (const float*)d_in[17];
    const float* l1_w      = (const float*)d_in[18];
    const float* l1_b      = (const float*)d_in[19];
    const float* l2_w      = (const float*)d_in[20];
    const float* l2_b      = (const float*)d_in[21];
    const float* l3_w      = (const float*)d_in[22];
    const float* l3_b      = (const float*)d_in[23];

    const int B = in_sizes[0] / CIN;   // 32768

    __half *p_h1, *p_h2, *p_h3, *p_h4, *p_xfh, *p_x1h, *p_x2h;
    __half *p_b1h, *p_b2h;
    __half *p_l1wt, *p_l2wt, *p_l3wt, *p_hw12t, *p_hb12t, *p_hw22t, *p_hb22t;
    float *p_x3, *p_stats;
    cudaGetSymbolAddress((void**)&p_h1, g_h1);
    cudaGetSymbolAddress((void**)&p_h2, g_h2);
    cudaGetSymbolAddress((void**)&p_h3, g_h3);
    cudaGetSymbolAddress((void**)&p_h4, g_h4);
    cudaGetSymbolAddress((void**)&p_xfh, g_xfh);
    cudaGetSymbolAddress((void**)&p_x1h, g_x1h);
    cudaGetSymbolAddress((void**)&p_x2h, g_x2h);
    cudaGetSymbolAddress((void**)&p_b1h, g_b1h);
    cudaGetSymbolAddress((void**)&p_b2h, g_b2h);
    cudaGetSymbolAddress((void**)&p_x3, g_x3);
    cudaGetSymbolAddress((void**)&p_stats, g_stats);
    cudaGetSymbolAddress((void**)&p_l1wt, g_l1wt);
    cudaGetSymbolAddress((void**)&p_l2wt, g_l2wt);
    cudaGetSymbolAddress((void**)&p_l3wt, g_l3wt);
    cudaGetSymbolAddress((void**)&p_hw12t, g_hw12t);
    cudaGetSymbolAddress((void**)&p_hb12t, g_hb12t);
    cudaGetSymbolAddress((void**)&p_hw22t, g_hw22t);
    cudaGetSymbolAddress((void**)&p_hb22t, g_hb22t);

    float* ssum1 = p_stats;
    float* ssq1  = p_stats + B_MAX;
    float* ssum2 = p_stats + 2 * B_MAX;
    float* ssq2  = p_stats + 3 * B_MAX;

    constexpr int SMEM64 = 2 * 256 * (64 + 8) * 2;  // 73728
    cudaFuncSetAttribute((const void*)gemm_h<__half>, cudaFuncAttributeMaxDynamicSharedMemorySize, SMEM64);
    cudaFuncSetAttribute((const void*)gemm_h<float>,  cudaFuncAttributeMaxDynamicSharedMemorySize, SMEM64);

    dim3 tb(32, 8);
    const int mg = B / 128;

    // zero GN stat accumulators (graph-capturable async memset)
    cudaMemsetAsync(p_stats, 0, 4 * (size_t)B_MAX * sizeof(float), 0);

    transpose_k<<<dim3(H1 / 32, CIN / 32), tb>>>(l1_w, p_l1wt, CIN, H1);
    {
        size_t n4 = (size_t)B * CIN / 4;
        cvt_h_vec<<<(unsigned)((n4 + 255) / 256), 256>>>(x_feature, p_xfh, n4);
    }
    {
        dim3 hg((B * 32 + 255) / 256, 4);
        hyper_hidden4<<<hg, 256>>>(x_param,
                                   hw1_1_w, hw1_1_b, p_h1,
                                   hb1_1_w, hb1_1_b, p_h2,
                                   hw2_1_w, hw2_1_b, p_h3,
                                   hb2_1_w, hb2_1_b, p_h4, B);
    }

    // l1 big GEMM (+row stats)
    gemm_h<__half><<<dim3(H1 / 128, mg), 128, SMEM64>>>(
        B, H1, CIN, p_xfh, p_l1wt, l1_b, p_x1h, ssum1, ssq1);

    transpose4<<<dim3(H1 / 32, 1, 4), tb>>>(
        hw1_2_w, p_hw12t, H1,
        hb1_2_w, p_hb12t, H1,
        hw2_2_w, p_hw22t, H2,
        hb2_2_w, p_hb22t, H2);
    transpose_k<<<dim3(H2 / 32, H1 / 32), tb>>>(l2_w, p_l2wt, H1, H2);
    transpose_k<<<dim3(COUT / 32, H2 / 32), tb>>>(l3_w, p_l3wt, H2, COUT);

    // layer 1: b-GEMM materializes b1h; w-GEMM applies fused GN in place
    gemm_hyp<<<dim3(H1 / 128, mg), 128>>>(B, H1, p_h2, p_hb12t, hb1_2_b, p_b1h);
    gemm_hyp_gn<<<dim3(H1 / 128, mg), 128>>>(
        B, H1, p_h1, p_hw12t, hw1_2_b, ssum1, ssq1, p_b1h, p_x1h);

    // l2 big GEMM (+row stats)
    gemm_h<__half><<<dim3(H2 / 128, mg), 128, SMEM64>>>(
        B, H2, H1, p_x1h, p_l2wt, l2_b, p_x2h, ssum2, ssq2);

    // layer 2: b-GEMM + fused w-GEMM/GN
    gemm_hyp<<<dim3(H2 / 128, mg), 128>>>(B, H2, p_h4, p_hb22t, hb2_2_b, p_b2h);
    gemm_hyp_gn<<<dim3(H2 / 128, mg), 128>>>(
        B, H2, p_h3, p_hw22t, hw2_2_b, ssum2, ssq2, p_b2h, p_x2h);

    // l3 GEMM -> fp32 x3 (no stats)
    gemm_h<float><<<dim3(COUT / 128, mg), 128, SMEM64>>>(
        B, COUT, H2, p_x2h, p_l3wt, l3_b, p_x3, nullptr, nullptr);

    // log_softmax -> output
    logsoftmax256<<<B, 256>>>(p_x3, (float*)d_out);
}